// round 5
// baseline (speedup 1.0000x reference)
#include <cuda_runtime.h>
#include <cuda_bf16.h>
#include <cstdint>

// CenterLoss:
//   loss = ( sum_b clamp(||x_b - centers[labels[b]]||^2, 1e-12, 1e12)
//            + B*(C-1)*1e-12 ) / B
// Only the labeled entry of the masked distance matrix is nonzero; the
// remaining B*(C-1) zeros clamp up to 1e-12 and contribute a constant.
//
// NOTE: JAX demotes int64 -> int32 by default, so labels is int32 on device.

__global__ void cl_init_kernel(float* __restrict__ out, float base) {
    if (threadIdx.x == 0 && blockIdx.x == 0) out[0] = base;
}

__global__ void __launch_bounds__(256)
cl_main_kernel(const float* __restrict__ x,
               const int* __restrict__ labels,
               const float* __restrict__ centers,
               float* __restrict__ out,
               int B, int D4, float inv_b) {
    int gwarp = (blockIdx.x * blockDim.x + threadIdx.x) >> 5;
    int lane  = threadIdx.x & 31;
    if (gwarp >= B) return;

    size_t lbl = (size_t)labels[gwarp];
    const float4* __restrict__ xr = reinterpret_cast<const float4*>(x) +
                                    (size_t)gwarp * D4;
    const float4* __restrict__ cr = reinterpret_cast<const float4*>(centers) +
                                    lbl * (size_t)D4;

    float acc = 0.0f;
    // D=512 -> D4=128 float4 per row -> 4 iterations per lane, coalesced.
    #pragma unroll 4
    for (int i = lane; i < D4; i += 32) {
        float4 a = xr[i];
        float4 b = cr[i];
        float d0 = a.x - b.x;
        float d1 = a.y - b.y;
        float d2 = a.z - b.z;
        float d3 = a.w - b.w;
        acc = fmaf(d0, d0, acc);
        acc = fmaf(d1, d1, acc);
        acc = fmaf(d2, d2, acc);
        acc = fmaf(d3, d3, acc);
    }

    // warp tree reduce
    #pragma unroll
    for (int o = 16; o > 0; o >>= 1)
        acc += __shfl_xor_sync(0xffffffffu, acc, o);

    if (lane == 0) {
        float v = fminf(fmaxf(acc, 1e-12f), 1e12f);
        atomicAdd(out, v * inv_b);
    }
}

extern "C" void kernel_launch(void* const* d_in, const int* in_sizes, int n_in,
                              void* d_out, int out_size) {
    const float* x       = (const float*)d_in[0];
    const int*   labels  = (const int*)d_in[1];
    const float* centers = (const float*)d_in[2];
    float*       out     = (float*)d_out;

    int B = in_sizes[1];              // 4096
    int D = in_sizes[0] / B;          // 512
    int C = in_sizes[2] / D;          // 10000
    int D4 = D >> 2;

    // Constant from the B*(C-1) masked zeros clamped to 1e-12, pre-divided by B.
    float base  = (float)((double)(C - 1) * 1e-12);
    float inv_b = 1.0f / (float)B;

    cl_init_kernel<<<1, 32>>>(out, base);

    const int THREADS = 256;                 // 8 warps/block -> 8 rows/block
    int blocks = (B * 32 + THREADS - 1) / THREADS;  // 512 blocks
    cl_main_kernel<<<blocks, THREADS>>>(x, labels, centers, out, B, D4, inv_b);
}

// round 8
// speedup vs baseline: 1.5346x; 1.5346x over previous
#include <cuda_runtime.h>
#include <cuda_bf16.h>
#include <cstdint>

// CenterLoss:
//   loss = ( sum_b ||x_b - centers[labels[b]]||^2 + B*(C-1)*1e-12 ) / B
// (clamp(.,1e-12,1e12) on the labeled entries is a no-op for non-degenerate
//  inputs: dist ~ 2*D ~ 1024 >> 1e-12; the B*(C-1) masked zeros clamp up to
//  1e-12 and contribute the constant base term.)
//
// Element-parallel formulation: flat reduction over B*D/4 float4 pairs so the
// label->gather dependency latency is hidden by ~56 warps/SM instead of being
// the per-warp critical path.

__global__ void cl_init_kernel(float* __restrict__ out, float base) {
    out[0] = base;
}

__global__ void __launch_bounds__(256)
cl_main_kernel(const float* __restrict__ x,
               const int* __restrict__ labels,
               const float* __restrict__ centers,
               float* __restrict__ out,
               int E, int D4, int shift, float inv_b) {
    const float4* __restrict__ x4 = reinterpret_cast<const float4*>(x);
    const float4* __restrict__ c4 = reinterpret_cast<const float4*>(centers);

    int total = gridDim.x * blockDim.x;
    float acc = 0.0f;

    for (int e = blockIdx.x * blockDim.x + threadIdx.x; e < E; e += total) {
        int b = (shift >= 0) ? (e >> shift) : (e / D4);
        int i = e - b * D4;
        int lbl = labels[b];                       // warp-broadcast (rows span 4 warps)
        float4 a  = x4[(size_t)e];                 // e == b*D4 + i, rows contiguous
        float4 cc = c4[(size_t)lbl * D4 + i];
        float d0 = a.x - cc.x;
        float d1 = a.y - cc.y;
        float d2 = a.z - cc.z;
        float d3 = a.w - cc.w;
        acc = fmaf(d0, d0, acc);
        acc = fmaf(d1, d1, acc);
        acc = fmaf(d2, d2, acc);
        acc = fmaf(d3, d3, acc);
    }

    // intra-warp reduce
    #pragma unroll
    for (int o = 16; o > 0; o >>= 1)
        acc += __shfl_xor_sync(0xffffffffu, acc, o);

    // inter-warp reduce via smem, one atomic per block
    __shared__ float wsum[8];
    int wid  = threadIdx.x >> 5;
    int lane = threadIdx.x & 31;
    if (lane == 0) wsum[wid] = acc;
    __syncthreads();
    if (wid == 0) {
        float v = (lane < (blockDim.x >> 5)) ? wsum[lane] : 0.0f;
        #pragma unroll
        for (int o = 4; o > 0; o >>= 1)
            v += __shfl_xor_sync(0xffffffffu, v, o);
        if (lane == 0) atomicAdd(out, v * inv_b);
    }
}

extern "C" void kernel_launch(void* const* d_in, const int* in_sizes, int n_in,
                              void* d_out, int out_size) {
    const float* x       = (const float*)d_in[0];
    const int*   labels  = (const int*)d_in[1];
    const float* centers = (const float*)d_in[2];
    float*       out     = (float*)d_out;

    int B  = in_sizes[1];              // 4096
    int D  = in_sizes[0] / B;          // 512
    int C  = in_sizes[2] / D;          // 10000
    int D4 = D >> 2;                   // 128
    int E  = B * D4;                   // 524288 float4 pairs

    // shift path when D4 is a power of two (it is: 128)
    int shift = -1;
    if ((D4 & (D4 - 1)) == 0) {
        shift = 0;
        while ((1 << shift) != D4) shift++;
    }

    float base  = (float)((double)(C - 1) * 1e-12);  // masked-zero clamp constant (pre /B)
    float inv_b = 1.0f / (float)B;

    cl_init_kernel<<<1, 1>>>(out, base);

    const int THREADS = 256;
    const int ELEMS_PER_THREAD = 2;
    int blocks = (E + THREADS * ELEMS_PER_THREAD - 1) / (THREADS * ELEMS_PER_THREAD);
    if (blocks < 1) blocks = 1;
    cl_main_kernel<<<blocks, THREADS>>>(x, labels, centers, out,
                                        E, D4, shift, inv_b);
}